// round 6
// baseline (speedup 1.0000x reference)
#include <cuda_runtime.h>
#include <cuda_fp16.h>

// Problem constants (fixed by reference setup_inputs)
#define B_  8
#define C_  3
#define H_  1024
#define W_  1024
#define HO_ 256
#define WO_ 256
#define KS_ 3
#define KK_ (KS_*KS_)    // 9
#define SCALE_ 4
#define HP_ (H_ + 2)     // padded 1026
#define WP_ (W_ + 2)
#define PLANE_ (H_*W_)   // 1M

// fp16 NHWC4 scratch: (B, H, W) pixels of 8B (half c0,c1,c2,pad) = 67.1 MB
// Viewed as uint4 (2 pixels) for wide access.
__device__ uint4 g_img_h4[B_ * H_ * 512];

// ---------------------------------------------------------------------------
// Pre-pass: NCHW fp32 -> NHWC4 fp16. 4 pixels per thread, fully coalesced.
// ---------------------------------------------------------------------------
__global__ __launch_bounds__(256)
void nchw_to_nhwc4h_kernel(const float* __restrict__ img)
{
    const int t  = blockIdx.x * blockDim.x + threadIdx.x;  // 0 .. B*H*W/4-1
    const int px = t * 4;
    const int b   = px >> 20;                              // / (H*W)
    const int rem = px & (PLANE_ - 1);

    const float* base = img + (long long)b * 3 * PLANE_ + rem;
    const float4 c0 = *(const float4*)(base);
    const float4 c1 = *(const float4*)(base + PLANE_);
    const float4 c2 = *(const float4*)(base + 2 * PLANE_);

    __half2 a0 = __floats2half2_rn(c0.x, c1.x);
    __half2 a1 = __floats2half2_rn(c2.x, 0.f);
    __half2 b0 = __floats2half2_rn(c0.y, c1.y);
    __half2 b1 = __floats2half2_rn(c2.y, 0.f);
    __half2 d0 = __floats2half2_rn(c0.z, c1.z);
    __half2 d1 = __floats2half2_rn(c2.z, 0.f);
    __half2 e0 = __floats2half2_rn(c0.w, c1.w);
    __half2 e1 = __floats2half2_rn(c2.w, 0.f);

    uint4 v0, v1;
    v0.x = *(unsigned*)&a0;  v0.y = *(unsigned*)&a1;
    v0.z = *(unsigned*)&b0;  v0.w = *(unsigned*)&b1;
    v1.x = *(unsigned*)&d0;  v1.y = *(unsigned*)&d1;
    v1.z = *(unsigned*)&e0;  v1.w = *(unsigned*)&e1;

    uint4* dst = g_img_h4 + (px >> 1);
    dst[0] = v0;
    dst[1] = v1;
}

// reflect-map a padded index (0..n+1) to original index (0..n-1), pad=1
__device__ __forceinline__ int reflect_map(int i, int n) {
    int j = i - 1;
    j = (j < 0) ? -j : j;
    j = (j >= n) ? (2 * n - 2 - j) : j;
    return j;
}

// unpack one 8B pixel (2x half2) -> 3 floats
__device__ __forceinline__ float3 unpack_px(unsigned lo, unsigned hi) {
    const float2 a = __half22float2(*(__half2*)&lo);
    const float2 b = __half22float2(*(__half2*)&hi);
    return make_float3(a.x, a.y, b.x);
}

// ---------------------------------------------------------------------------
// Main pass: merged corner-pair gathers, fp32 accumulate.
// ---------------------------------------------------------------------------
__global__ __launch_bounds__(256, 5)
void adaptive_downsample_kernel(
    const float* __restrict__ kernels,    // (B,9,HO,WO)
    const float* __restrict__ offs_h,     // (B,9,HO,WO)
    const float* __restrict__ offs_v,     // (B,9,HO,WO)
    const float* __restrict__ offset_unit,// (1,)
    float* __restrict__ out)              // (B,C,HO,WO)
{
    const int ow = blockIdx.x * blockDim.x + threadIdx.x;  // 0..255
    const int oh = blockIdx.y * blockDim.y + threadIdx.y;  // 0..255
    const int b  = blockIdx.z;

    const float ou = __ldg(offset_unit);

    const float cy = ((float)oh + 0.5f) * (float)SCALE_ - 0.5f;
    const float cx = ((float)ow + 0.5f) * (float)SCALE_ - 0.5f;

    const int pix   = oh * WO_ + ow;
    const int plane = HO_ * WO_;                 // 65536
    const int auxb  = b * KK_ * plane + pix;

    // image base, in uint2 (=1 pixel) units; row pitch 1024 px
    const uint2* imgb2 = (const uint2*)g_img_h4 + ((size_t)b << 20);
    const uint4* imgb4 = g_img_h4 + ((size_t)b << 19);

    float acc0 = 0.f, acc1 = 0.f, acc2 = 0.f;

    #pragma unroll
    for (int k = 0; k < KK_; ++k) {
        const float kw  = __ldg(kernels + auxb + k * plane);
        const float ovv = __ldg(offs_v  + auxb + k * plane);
        const float ohh = __ldg(offs_h  + auxb + k * plane);

        const float py = cy + (float)(k / KS_) + ovv * ou;
        const float px = cx + (float)(k % KS_) + ohh * ou;

        const float y0f = floorf(py);
        const float x0f = floorf(px);
        const float beta  = py - y0f;
        const float alpha = px - x0f;

        int y0 = (int)y0f;  y0 = min(max(y0, 0), HP_ - 1);
        int y1 = min(y0 + 1, HP_ - 1);
        int x0 = (int)x0f;  x0 = min(max(x0, 0), WP_ - 1);
        int x1 = min(x0 + 1, WP_ - 1);

        const int ry0 = reflect_map(y0, H_);
        const int ry1 = reflect_map(y1, H_);
        const int rx0 = reflect_map(x0, W_);
        const int rx1 = reflect_map(x1, W_);

        // merged x-pair: m = min corner, pair (m, m+1) always contains both
        // corners (interior: ordered; boundary: reversed or equal)
        const int m   = min(rx0, rx1);            // 0..1022
        const int e   = m & ~1;                   // even base pixel
        const bool odd = (m & 1);

        // weight of loaded pixel P[m]; P[m+1] gets the complement
        // (x-weights sum to 1: (1-alpha) + alpha)
        const float wl = (rx0 == m ? (1.f - alpha) : 0.f)
                       + (rx1 == m ? alpha : 0.f);
        const float wh = 1.f - wl;

        const float kb0 = kw * (1.f - beta);
        const float kb1 = kw * beta;
        const float Wl0 = kb0 * wl, Wh0 = kb0 * wh;
        const float Wl1 = kb1 * wl, Wh1 = kb1 * wh;

        // full loads: 2 pixels (e, e+1) per row
        const uint4 r0 = __ldg(imgb4 + ((ry0 << 10) + e >> 1));
        const uint4 r1 = __ldg(imgb4 + ((ry1 << 10) + e >> 1));

        // predicated extra load for odd m: pixel m+1
        uint2 s0 = make_uint2(0u, 0u), s1 = make_uint2(0u, 0u);
        if (odd) {
            s0 = __ldg(imgb2 + (ry0 << 10) + m + 1);
            s1 = __ldg(imgb2 + (ry1 << 10) + m + 1);
        }

        // select pixel values: P[m] and P[m+1] per row
        const unsigned pm0_lo = odd ? r0.z : r0.x, pm0_hi = odd ? r0.w : r0.y;
        const unsigned ph0_lo = odd ? s0.x : r0.z, ph0_hi = odd ? s0.y : r0.w;
        const unsigned pm1_lo = odd ? r1.z : r1.x, pm1_hi = odd ? r1.w : r1.y;
        const unsigned ph1_lo = odd ? s1.x : r1.z, ph1_hi = odd ? s1.y : r1.w;

        const float3 Pm0 = unpack_px(pm0_lo, pm0_hi);
        const float3 Ph0 = unpack_px(ph0_lo, ph0_hi);
        const float3 Pm1 = unpack_px(pm1_lo, pm1_hi);
        const float3 Ph1 = unpack_px(ph1_lo, ph1_hi);

        acc0 = fmaf(Wl0, Pm0.x, fmaf(Wh0, Ph0.x, fmaf(Wl1, Pm1.x, fmaf(Wh1, Ph1.x, acc0))));
        acc1 = fmaf(Wl0, Pm0.y, fmaf(Wh0, Ph0.y, fmaf(Wl1, Pm1.y, fmaf(Wh1, Ph1.y, acc1))));
        acc2 = fmaf(Wl0, Pm0.z, fmaf(Wh0, Ph0.z, fmaf(Wl1, Pm1.z, fmaf(Wh1, Ph1.z, acc2))));
    }

    const int ob = b * C_ * plane + pix;
    out[ob]             = acc0;
    out[ob + plane]     = acc1;
    out[ob + 2 * plane] = acc2;
}

extern "C" void kernel_launch(void* const* d_in, const int* in_sizes, int n_in,
                              void* d_out, int out_size) {
    const float* img     = (const float*)d_in[0];
    const float* kernels = (const float*)d_in[1];
    const float* offs_h  = (const float*)d_in[2];
    const float* offs_v  = (const float*)d_in[3];
    const float* ou      = (const float*)d_in[4];
    float* out = (float*)d_out;

    // Pre-pass: B*H*W/4 threads, 4 px each
    const int n_threads = B_ * H_ * W_ / 4;     // 2.1M
    nchw_to_nhwc4h_kernel<<<n_threads / 256, 256>>>(img);

    dim3 block(32, 8, 1);
    dim3 grid(WO_ / 32, HO_ / 8, B_);
    adaptive_downsample_kernel<<<grid, block>>>(kernels, offs_h, offs_v, ou, out);
}